// round 13
// baseline (speedup 1.0000x reference)
#include <cuda_runtime.h>
#include <cuda_fp16.h>
#include <math.h>
#include <cstdint>

typedef __half f16;

// Problem constants
#define B_  2
#define KQ  1024
#define SQ  4096
#define D_  1024
#define H_  16
#define HD_ 64
#define EPSV 1e-5f

// ================= scratch (static device globals) =================
__device__ float g_x  [B_*KQ*D_];
__device__ f16   g_biasc[B_*KQ*SQ];

__device__ f16 g_lnq [B_*KQ*D_];
__device__ f16 g_lnkv[B_*SQ*D_];
__device__ f16 g_Qh[B_*KQ*D_];
__device__ f16 g_Kh[B_*SQ*D_];
__device__ f16 g_Vh[B_*SQ*D_];
__device__ f16 g_att[B_*KQ*D_];
__device__ f16 g_h1 [B_*KQ*2*D_];
__device__ f16 g_wqt[D_*D_];
__device__ f16 g_wkt[D_*D_];
__device__ f16 g_wvt[D_*D_];
__device__ f16 g_wot[D_*D_];
__device__ f16 g_w1t[2*D_*D_];
__device__ f16 g_w2t[2*D_*D_];

__device__ __forceinline__ float softplus_f(float x) {
    return fmaxf(x, 0.f) + log1pf(__expf(-fabsf(x)));
}
__device__ __forceinline__ float gelu_f(float x) {
    return 0.5f * x * (1.f + erff(x * 0.70710678118654752f));
}
__device__ __forceinline__ uint32_t smem_to_u32(const void* p) {
    uint32_t a;
    asm("{ .reg .u64 t; cvta.to.shared.u64 t, %1; cvt.u32.u64 %0, t; }" : "=r"(a) : "l"(p));
    return a;
}
__device__ __forceinline__ uint32_t cvt2_f16(float lo, float hi) {
    uint32_t r; asm("cvt.rn.f16x2.f32 %0, %1, %2;" : "=r"(r) : "f"(hi), "f"(lo)); return r;
}
__device__ __forceinline__ uint32_t ex2_h2(uint32_t t) {
    uint32_t r; asm("ex2.approx.f16x2 %0, %1;" : "=r"(r) : "r"(t)); return r;
}

// cp.async helpers
#define CP_ASYNC16(dst, src) \
    asm volatile("cp.async.cg.shared.global [%0], [%1], 16;" :: "r"(dst), "l"(src))
#define CP_COMMIT() asm volatile("cp.async.commit_group;" ::: "memory")
#define CP_WAIT3()  asm volatile("cp.async.wait_group 3;" ::: "memory")
#define CP_WAIT2()  asm volatile("cp.async.wait_group 2;" ::: "memory")
#define CP_WAIT1()  asm volatile("cp.async.wait_group 1;" ::: "memory")
#define CP_WAIT0()  asm volatile("cp.async.wait_group 0;" ::: "memory")

#define LDSM_X4(r0, r1, r2, r3, addr) \
    asm volatile("ldmatrix.sync.aligned.m8n8.x4.shared.b16 {%0,%1,%2,%3}, [%4];" \
        : "=r"(r0), "=r"(r1), "=r"(r2), "=r"(r3) : "r"(addr))
#define LDSM_X4_T(r0, r1, r2, r3, addr) \
    asm volatile("ldmatrix.sync.aligned.m8n8.x4.trans.shared.b16 {%0,%1,%2,%3}, [%4];" \
        : "=r"(r0), "=r"(r1), "=r"(r2), "=r"(r3) : "r"(addr))

#define MMA_16816(c, a, b) \
    asm volatile("mma.sync.aligned.m16n8k16.row.col.f32.f16.f16.f32 " \
        "{%0,%1,%2,%3}, {%4,%5,%6,%7}, {%8,%9}, {%0,%1,%2,%3};" \
        : "+f"((c)[0]), "+f"((c)[1]), "+f"((c)[2]), "+f"((c)[3]) \
        : "r"((a)[0]), "r"((a)[1]), "r"((a)[2]), "r"((a)[3]), "r"((b)[0]), "r"((b)[1]))

// ================= prep: weight transpose->fp16 + combined bias (f16) =========
struct PrepArgs {
    const float* wsrc[6];
    f16* wdst[6];
    int K[6]; int N[6];
    const float* ab; const float* ob; const float* pd; const float* po;
    f16* biasc;
};
__global__ void prep_k(PrepArgs a) {
    int z = blockIdx.z;
    int tx = threadIdx.x, ty = threadIdx.y;
    if (z < 6) {
        int Kd = a.K[z], Nd = a.N[z];
        int n0 = blockIdx.x * 32, k0 = blockIdx.y * 32;
        if (n0 >= Nd || k0 >= Kd) return;
        __shared__ float t[32][33];
        const float* s = a.wsrc[z];
#pragma unroll
        for (int i = 0; i < 4; i++)
            t[ty + i*8][tx] = s[(size_t)(k0 + ty + i*8) * Nd + n0 + tx];
        __syncthreads();
#pragma unroll
        for (int i = 0; i < 4; i++) {
            float v = t[tx][ty + i*8];
            a.wdst[z][(size_t)(n0 + ty + i*8) * Kd + k0 + tx] = __float2half_rn(v);
        }
    } else {
        int cta = blockIdx.y * 64 + blockIdx.x;
        int tid = ty * 32 + tx;
        float spd = softplus_f(a.pd[0]);
        float spo = softplus_f(a.po[0]);
        size_t base = (size_t)cta * 512 + tid * 2;
#pragma unroll
        for (int j = 0; j < 2; j++) {
            float4 av = ((const float4*)a.ab)[base + j];
            float4 ov = ((const float4*)a.ob)[base + j];
            __half2 h0 = __floats2half2_rn(spd*av.x + spo*ov.x, spd*av.y + spo*ov.y);
            __half2 h1 = __floats2half2_rn(spd*av.z + spo*ov.z, spd*av.w + spo*ov.w);
            ((__half2*)a.biasc)[(base + j)*2 + 0] = h0;
            ((__half2*)a.biasc)[(base + j)*2 + 1] = h1;
        }
    }
}

// ================= LayerNorm -> fp16 =================
__device__ __forceinline__ void ln_body(const float* xr, const float* w, const float* bb,
                                        f16* yr) {
    __shared__ float r0[8], r1[8];
    __shared__ float mu_s, rs_s;
    int t = threadIdx.x;
    float v[4]; float s = 0.f, s2 = 0.f;
#pragma unroll
    for (int i = 0; i < 4; i++) { float a = xr[t + i*256]; v[i] = a; s += a; s2 += a*a; }
    int lane = t & 31, wp = t >> 5;
#pragma unroll
    for (int o = 16; o; o >>= 1) {
        s  += __shfl_xor_sync(0xffffffffu, s,  o);
        s2 += __shfl_xor_sync(0xffffffffu, s2, o);
    }
    if (lane == 0) { r0[wp] = s; r1[wp] = s2; }
    __syncthreads();
    if (t == 0) {
        float ts = 0.f, t2 = 0.f;
        for (int i = 0; i < 8; i++) { ts += r0[i]; t2 += r1[i]; }
        float mu = ts * (1.f / D_);
        float var = t2 * (1.f / D_) - mu * mu;
        mu_s = mu; rs_s = rsqrtf(var + EPSV);
    }
    __syncthreads();
    float mu = mu_s, rs = rs_s;
#pragma unroll
    for (int i = 0; i < 4; i++) {
        int c = t + i*256;
        yr[c] = __float2half_rn((v[i] - mu) * rs * w[c] + bb[c]);
    }
}

__global__ void ln_all_k(const float* __restrict__ q, const float* __restrict__ kv,
                         const float* __restrict__ wq, const float* __restrict__ bq,
                         const float* __restrict__ wkv, const float* __restrict__ bkv,
                         f16* __restrict__ oq, f16* __restrict__ okv) {
    int row = blockIdx.x;
    if (row < B_*KQ) ln_body(q + (size_t)row * D_, wq, bq, oq + (size_t)row * D_);
    else {
        row -= B_*KQ;
        ln_body(kv + (size_t)row * D_, wkv, bkv, okv + (size_t)row * D_);
    }
}

__global__ void ln_one_k(const float* __restrict__ x, const float* __restrict__ w,
                         const float* __restrict__ bb, f16* __restrict__ y) {
    int row = blockIdx.x;
    ln_body(x + (size_t)row * D_, w, bb, y + (size_t)row * D_);
}

// ================= HMMA fp16 GEMM core (templated BM = 128 or 64) ==========
// mode 1: gelu -> Chi.  mode 2: +R -> Cf fp32.  mode 4: Chi.
#define GPAD 40
#define GSTG 4

template<int BM>
__device__ __forceinline__ void gemm_core(
        int mode, char* gsm,
        const f16* __restrict__ Ag, const f16* __restrict__ Bg,
        const float* __restrict__ bias, const float* __restrict__ R,
        float* __restrict__ Cf, f16* __restrict__ Chi,
        int m0, int n0, int N, int Kd) {
    constexpr int NI = (BM == 128) ? 8 : 4;      // n-frags per warp
    constexpr int NW = (BM == 128) ? 64 : 32;    // warp n-width
    constexpr int ABUF = BM * GPAD;              // A f16 elems per stage
    constexpr int BBUF = 128 * GPAD;             // B f16 elems per stage
    constexpr int STRIDE = (ABUF + BBUF) * 2;    // bytes per stage

    int tid = threadIdx.x, lane = tid & 31, wid = tid >> 5;
    int wm = (BM == 128) ? (wid & 3) : (wid & 1);
    int wn = (BM == 128) ? (wid >> 2) : (wid >> 1);
    uint32_t sbase = smem_to_u32(gsm);

    float c[2][NI][4];
#pragma unroll
    for (int i = 0; i < 2; i++)
#pragma unroll
        for (int j = 0; j < NI; j++)
#pragma unroll
            for (int q = 0; q < 4; q++) c[i][j][q] = 0.f;

    int nch = Kd >> 5;
    int lr = tid >> 2;
    int ls = (tid & 3) << 3;

    auto prefetch = [&](int ch, int buf) {
        int kc = ch << 5;
        uint32_t st = sbase + (uint32_t)buf * STRIDE;
        uint32_t db = st + ABUF*2;
        CP_ASYNC16(st + (lr*GPAD + ls)*2,      Ag + (size_t)(m0 + lr)      * Kd + kc + ls);
        if (BM == 128)
            CP_ASYNC16(st + ((lr+64)*GPAD + ls)*2, Ag + (size_t)(m0 + lr + 64) * Kd + kc + ls);
        CP_ASYNC16(db + (lr*GPAD + ls)*2,      Bg + (size_t)(n0 + lr)      * Kd + kc + ls);
        CP_ASYNC16(db + ((lr+64)*GPAD + ls)*2, Bg + (size_t)(n0 + lr + 64) * Kd + kc + ls);
    };

#pragma unroll
    for (int s = 0; s < GSTG; s++) { prefetch(s, s); CP_COMMIT(); }

    for (int it = 0; it < nch; ++it) {
        int cur = it & (GSTG - 1);
        int rem = nch - 1 - it;
        if (rem >= 3) CP_WAIT3();
        else if (rem == 2) CP_WAIT2();
        else if (rem == 1) CP_WAIT1();
        else CP_WAIT0();
        __syncthreads();

        uint32_t st = sbase + (uint32_t)cur * STRIDE;
        uint32_t bb = st + ABUF*2;
#pragma unroll
        for (int kk = 0; kk < 32; kk += 16) {
            uint32_t a[2][4];
#pragma unroll
            for (int mi = 0; mi < 2; mi++) {
                int row = wm*32 + mi*16 + ((lane >> 3) & 1)*8 + (lane & 7);
                int col = kk + (lane >> 4)*8;
                LDSM_X4(a[mi][0], a[mi][1], a[mi][2], a[mi][3],
                        st + (uint32_t)(row*GPAD + col)*2);
            }
            uint32_t b[NI][2];
#pragma unroll
            for (int g = 0; g < NI/2; g++) {
                int row = wn*NW + g*16 + (lane >> 4)*8 + (lane & 7);
                int col = kk + ((lane >> 3) & 1)*8;
                uint32_t r0, r1, r2, r3;
                LDSM_X4(r0, r1, r2, r3, bb + (uint32_t)(row*GPAD + col)*2);
                b[2*g][0] = r0; b[2*g][1] = r1;
                b[2*g+1][0] = r2; b[2*g+1][1] = r3;
            }
#pragma unroll
            for (int mi = 0; mi < 2; mi++)
#pragma unroll
                for (int ni = 0; ni < NI; ni++)
                    MMA_16816(c[mi][ni], a[mi], b[ni]);
        }
        __syncthreads();
        if (it + GSTG < nch) { prefetch(it + GSTG, cur); CP_COMMIT(); }
    }

#pragma unroll
    for (int mi = 0; mi < 2; mi++) {
#pragma unroll
        for (int half = 0; half < 2; half++) {
            int row = m0 + wm*32 + mi*16 + half*8 + (lane >> 2);
#pragma unroll
            for (int ni = 0; ni < NI; ni++) {
                int col = n0 + wn*NW + ni*8 + (lane & 3)*2;
                float v0 = c[mi][ni][half*2 + 0] + bias[col];
                float v1 = c[mi][ni][half*2 + 1] + bias[col + 1];
                size_t idx = (size_t)row * N + col;
                if (mode == 1) {
                    v0 = gelu_f(v0); v1 = gelu_f(v1);
                    *(uint32_t*)(Chi + idx) = cvt2_f16(v0, v1);
                } else if (mode == 4) {
                    *(uint32_t*)(Chi + idx) = cvt2_f16(v0, v1);
                } else {  // mode 2
                    float2 r2 = *(const float2*)(R + idx);
                    float2 o2; o2.x = v0 + r2.x; o2.y = v1 + r2.y;
                    *(float2*)(Cf + idx) = o2;
                }
            }
        }
    }
}

#define GT_SMEM128 (GSTG*(128+128)*GPAD*2)   // 81920
#define GT_SMEM64  (GSTG*(64+128)*GPAD*2)    // 61440

__global__ void __launch_bounds__(256, 2) gemm_g(
        int mode, const f16* Ag, const f16* Bg,
        const float* bias, const float* R,
        float* Cf, f16* Chi, int N, int Kd) {
    extern __shared__ char gsm[];
    gemm_core<128>(mode, gsm, Ag, Bg, bias, R, Cf, Chi,
                   blockIdx.y * 128, blockIdx.x * 128, N, Kd);
}

__global__ void __launch_bounds__(256, 2) gemm_g64(
        int mode, const f16* Ag, const f16* Bg,
        const float* bias, const float* R,
        float* Cf, f16* Chi, int N, int Kd) {
    extern __shared__ char gsm[];
    gemm_core<64>(mode, gsm, Ag, Bg, bias, R, Cf, Chi,
                  blockIdx.y * 64, blockIdx.x * 128, N, Kd);
}

__global__ void __launch_bounds__(256, 2) qkv_k(
        const f16* lnq, const f16* lnkv,
        const f16* wq, const f16* wk, const f16* wv,
        const float* bq, const float* bk, const float* bv,
        f16* Qh, f16* Kh, f16* Vh) {
    extern __shared__ char gsm[];
    int y = blockIdx.y;
    const f16 *A, *Bw; const float* bias; f16 *Ch; int m0;
    if (y < 16)      { A = lnq;  Bw = wq; bias = bq; Ch = Qh; m0 = y * 128; }
    else if (y < 80) { A = lnkv; Bw = wk; bias = bk; Ch = Kh; m0 = (y - 16) * 128; }
    else             { A = lnkv; Bw = wv; bias = bv; Ch = Vh; m0 = (y - 80) * 128; }
    gemm_core<128>(4, gsm, A, Bw, bias, nullptr, nullptr, Ch,
                   m0, blockIdx.x * 128, D_, D_);
}

// ================= Flash attention: fixed-shift softmax, 128-s iterations ===
// p = 2^((score-4)*log2e) unnormalized; l accumulated from realized f16 p.
#define NIT   (SQ/128)            // 32
#define APCH  144
#define AQ_H  0
#define AKV   (128*APCH)          // 18432
#define AKVARR (128*APCH)         // 18432 per array (128 s-rows)
#define AKVBUF (2*AKVARR)         // 36864 per stage (Kh,Vh)
#define ASTG  2
#define AGATE (AKV + ASTG*AKVBUF) // 92160
#define ATT_SMEM (AGATE + 512)

#define LOG2E 1.4426950408889634f
#define MSHIFT (-4.0f * LOG2E)

__global__ void __launch_bounds__(256, 2) attn_mma_k(
        const f16* __restrict__ Qhg,
        const f16* __restrict__ Khg,
        const f16* __restrict__ Vhg,
        const f16* __restrict__ bcp, const float* __restrict__ dens,
        const float* __restrict__ p_dens,
        f16* __restrict__ Oh) {
    extern __shared__ char smem[];
    uint32_t sb = smem_to_u32(smem);
    int tid = threadIdx.x, lane = tid & 31, w = tid >> 5;
    int qt = blockIdx.x, h = blockIdx.y, b = blockIdx.z;
    int q0 = qt * 128;
    size_t qrow0 = (size_t)(b * KQ + q0);
    size_t srow0 = (size_t)(b * SQ);
    int hoff = h * 64;

    // load Q tile 128x64 into smem
#pragma unroll
    for (int i = 0; i < 4; i++) {
        int idx = tid + i*256;
        int r = idx >> 3, cc = idx & 7;
        *(uint4*)(smem + AQ_H + r*APCH + cc*16) = *(const uint4*)(Qhg + (qrow0 + r)*D_ + hoff + cc*8);
    }
    if (tid < 128) {
        float* gp = (float*)(smem + AGATE);
        gp[tid] = 1.f + tanhf(p_dens[0]) * dens[b*KQ + q0 + tid];
    }

    // prefetch one 128-s stage of K,V
    auto pf = [&](int s0, int buf) {
        uint32_t base = sb + AKV + buf*AKVBUF;
#pragma unroll
        for (int j = 0; j < 4; j++) {
            int rem = tid + j*256;              // 0..1023
            int row = rem >> 3, cc = rem & 7;   // row 0..127
            size_t goff = (srow0 + s0 + row)*D_ + hoff + cc*8;
            uint32_t soff = (uint32_t)(row*APCH + cc*16);
            CP_ASYNC16(base + 0*AKVARR + soff, Khg + goff);
            CP_ASYNC16(base + 1*AKVARR + soff, Vhg + goff);
        }
    };
    pf(0, 0);   CP_COMMIT();
    pf(128, 1); CP_COMMIT();
    __syncthreads();   // Q tile + gate visible

    // preload Q fragments into registers (constant across iterations)
    uint32_t qf[4][4];
#pragma unroll
    for (int ki = 0; ki < 4; ki++) {
        uint32_t qaddr = sb + AQ_H + (uint32_t)((w*16 + (lane & 15))*APCH + (ki*16 + (lane >> 4)*8)*2);
        LDSM_X4(qf[ki][0], qf[ki][1], qf[ki][2], qf[ki][3], qaddr);
    }
    int r0 = w*16 + (lane >> 2), r1 = r0 + 8;
    float g0, g1;
    {
        float* gp = (float*)(smem + AGATE);
        g0 = gp[r0]; g1 = gp[r1];
    }
    float ga0 = g0 * 0.125f * LOG2E, gb0 = g0 * LOG2E;
    float ga1 = g1 * 0.125f * LOG2E, gb1 = g1 * LOG2E;

    float o[8][4];
#pragma unroll
    for (int i = 0; i < 8; i++)
#pragma unroll
        for (int j = 0; j < 4; j++) o[i][j] = 0.f;
    float2 l0f = {0.f, 0.f}, l1f = {0.f, 0.f};
    const f16* bp0 = bcp + (qrow0 + r0)*SQ + (lane & 3)*2;
    const f16* bp1 = bcp + (qrow0 + r1)*SQ + (lane & 3)*2;

    for (int it = 0; it < NIT; it++) {
        if (it + 1 < NIT) CP_WAIT1(); else CP_WAIT0();
        __syncthreads();
        uint32_t kvb = sb + AKV + (it & 1)*AKVBUF;

#pragma unroll
        for (int sc = 0; sc < 8; sc++) {   // s-chunks of 16 (128 s per iter)
            // ---- S chunk = Qh Kh ----
            float c2[2][4];
#pragma unroll
            for (int i = 0; i < 2; i++)
#pragma unroll
                for (int j = 0; j < 4; j++) c2[i][j] = 0.f;
#pragma unroll
            for (int ki = 0; ki < 4; ki++) {
                uint32_t kf[4];
                uint32_t kaddr = kvb + (uint32_t)((sc*16 + (lane & 15))*APCH + (ki*16 + (lane >> 4)*8)*2);
                LDSM_X4(kf[0], kf[1], kf[2], kf[3], kaddr);
                uint32_t B0[2] = { kf[0], kf[2] };
                uint32_t B1[2] = { kf[1], kf[3] };
                MMA_16816(c2[0], qf[ki], B0);
                MMA_16816(c2[1], qf[ki], B1);
            }
            // ---- bias + gate -> log2 domain -> ex2.f16x2 ----
            uint32_t pa[4];
#pragma unroll
            for (int half = 0; half < 2; half++) {
                int cb = it*128 + sc*16 + half*8;
                uint32_t u0 = *(const uint32_t*)(bp0 + cb);
                uint32_t u1 = *(const uint32_t*)(bp1 + cb);
                float2 b0 = __half22float2(*(const __half2*)&u0);
                float2 b1 = __half22float2(*(const __half2*)&u1);
                float t00 = fminf(fmaf(c2[half][0], ga0, fmaf(b0.x, gb0, MSHIFT)), 15.5f);
                float t01 = fminf(fmaf(c2[half][1], ga0, fmaf(b0.y, gb0, MSHIFT)), 15.5f);
                float t10 = fminf(fmaf(c2[half][2], ga1, fmaf(b1.x, gb1, MSHIFT)), 15.5f);
                float t11 = fminf(fmaf(c2[half][3], ga1, fmaf(b1.y, gb1, MSHIFT)), 15.5f);
                uint32_t p0 = ex2_h2(cvt2_f16(t00, t01));
                uint32_t p1 = ex2_h2(cvt2_f16(t10, t11));
                pa[half*2]     = p0;
                pa[half*2 + 1] = p1;
                float2 e0 = __half22float2(*(const __half2*)&p0);
                float2 e1 = __half22float2(*(const __half2*)&p1);
                l0f.x += e0.x; l0f.y += e0.y;
                l1f.x += e1.x; l1f.y += e1.y;
            }
            // ---- O += P V for this s-chunk ----
#pragma unroll
            for (int db = 0; db < 4; db++) {
                uint32_t vaddr = kvb + 1*AKVARR +
                    (uint32_t)((sc*16 + ((lane >> 3) & 1)*8 + (lane & 7))*APCH + (db*16 + (lane >> 4)*8)*2);
                uint32_t vh4[4];
                LDSM_X4_T(vh4[0], vh4[1], vh4[2], vh4[3], vaddr);
                uint32_t B0[2] = { vh4[0], vh4[1] };
                uint32_t B1[2] = { vh4[2], vh4[3] };
                MMA_16816(o[db*2],     pa, B0);
                MMA_16816(o[db*2 + 1], pa, B1);
            }
        }
        __syncthreads();
        if (it + 2 < NIT) { pf((it + 2)*128, it & 1); CP_COMMIT(); }
    }

    // ---- epilogue: reduce l across the quad, normalize, store ----
    float l0 = l0f.x + l0f.y, l1 = l1f.x + l1f.y;
    l0 += __shfl_xor_sync(0xffffffffu, l0, 1);
    l0 += __shfl_xor_sync(0xffffffffu, l0, 2);
    l1 += __shfl_xor_sync(0xffffffffu, l1, 1);
    l1 += __shfl_xor_sync(0xffffffffu, l1, 2);
    float inv0 = 1.f / l0, inv1 = 1.f / l1;
#pragma unroll
    for (int nf = 0; nf < 8; nf++) {
        int d = nf*8 + (lane & 3)*2;
        size_t i0 = (qrow0 + r0)*D_ + hoff + d;
        size_t i1 = (qrow0 + r1)*D_ + hoff + d;
        *(uint32_t*)(Oh + i0) = cvt2_f16(o[nf][0]*inv0, o[nf][1]*inv0);
        *(uint32_t*)(Oh + i1) = cvt2_f16(o[nf][2]*inv1, o[nf][3]*inv1);
    }
}

// ================= launch =================
extern "C" void kernel_launch(void* const* d_in, const int* in_sizes, int n_in,
                              void* d_out, int out_size) {
    const float* q        = (const float*)d_in[0];
    const float* kv       = (const float*)d_in[1];
    const float* attn_b   = (const float*)d_in[2];
    const float* obs_b    = (const float*)d_in[3];
    const float* density  = (const float*)d_in[4];
    const float* ln_q_w   = (const float*)d_in[5];
    const float* ln_q_b   = (const float*)d_in[6];
    const float* ln_kv_w  = (const float*)d_in[7];
    const float* ln_kv_b  = (const float*)d_in[8];
    const float* wq = (const float*)d_in[9];  const float* bq = (const float*)d_in[10];
    const float* wk = (const float*)d_in[11]; const float* bk = (const float*)d_in[12];
    const float* wv = (const float*)d_in[13]; const float* bv = (const float*)d_in[14];
    const float* wo = (const float*)d_in[15]; const float* bo = (const float*)d_in[16];
    const float* dist_raw = (const float*)d_in[17];
    const float* obs_raw  = (const float*)d_in[18];
    const float* dens_raw = (const float*)d_in[19];
    const float* ln_f_w = (const float*)d_in[20]; const float* ln_f_b = (const float*)d_in[21];
    const float* w1 = (const float*)d_in[22]; const float* b1 = (const float*)d_in[23];
    const float* w2 = (const float*)d_in[24]; const float* b2 = (const float*)d_in[25];
    float* out = (float*)d_out;

    float *x;
    f16 *biasc;
    cudaGetSymbolAddress((void**)&x,   g_x);
    cudaGetSymbolAddress((void**)&biasc, g_biasc);
    f16 *lnq, *lnkv, *att, *h1, *Qh, *Kh, *Vh;
    cudaGetSymbolAddress((void**)&lnq,  g_lnq);
    cudaGetSymbolAddress((void**)&lnkv, g_lnkv);
    cudaGetSymbolAddress((void**)&att,  g_att);
    cudaGetSymbolAddress((void**)&h1,   g_h1);
    cudaGetSymbolAddress((void**)&Qh, g_Qh);
    cudaGetSymbolAddress((void**)&Kh, g_Kh);
    cudaGetSymbolAddress((void**)&Vh, g_Vh);
    f16 *wt[6];
    cudaGetSymbolAddress((void**)&wt[0], g_wqt);
    cudaGetSymbolAddress((void**)&wt[1], g_wkt);
    cudaGetSymbolAddress((void**)&wt[2], g_wvt);
    cudaGetSymbolAddress((void**)&wt[3], g_wot);
    cudaGetSymbolAddress((void**)&wt[4], g_w1t);
    cudaGetSymbolAddress((void**)&wt[5], g_w2t);

    cudaFuncSetAttribute(gemm_g,     cudaFuncAttributeMaxDynamicSharedMemorySize, GT_SMEM128);
    cudaFuncSetAttribute(gemm_g64,   cudaFuncAttributeMaxDynamicSharedMemorySize, GT_SMEM64);
    cudaFuncSetAttribute(qkv_k,      cudaFuncAttributeMaxDynamicSharedMemorySize, GT_SMEM128);
    cudaFuncSetAttribute(attn_mma_k, cudaFuncAttributeMaxDynamicSharedMemorySize, ATT_SMEM);

    // [0] prep: weight transpose -> fp16 + combined bias (f16)
    PrepArgs pa;
    pa.wsrc[0] = wq; pa.wsrc[1] = wk; pa.wsrc[2] = wv; pa.wsrc[3] = wo; pa.wsrc[4] = w1; pa.wsrc[5] = w2;
    for (int i = 0; i < 6; i++) pa.wdst[i] = wt[i];
    pa.K[0]=1024; pa.K[1]=1024; pa.K[2]=1024; pa.K[3]=1024; pa.K[4]=1024; pa.K[5]=2048;
    pa.N[0]=1024; pa.N[1]=1024; pa.N[2]=1024; pa.N[3]=1024; pa.N[4]=2048; pa.N[5]=1024;
    pa.ab = attn_b; pa.ob = obs_b; pa.pd = dist_raw; pa.po = obs_raw; pa.biasc = biasc;
    prep_k<<<dim3(64, 64, 7), dim3(32, 8)>>>(pa);

    // [1] both input LayerNorms -> fp16
    ln_all_k<<<B_*(KQ + SQ), 256>>>(q, kv, ln_q_w, ln_q_b, ln_kv_w, ln_kv_b, lnq, lnkv);

    // [2] fused Q/K/V projections
    qkv_k<<<dim3(8, 144), 256, GT_SMEM128>>>(lnq, lnkv, wt[0], wt[1], wt[2],
                                             bq, bk, bv, Qh, Kh, Vh);

    // [3] flash attention -> att fp16   (captured by ncu)
    attn_mma_k<<<dim3(KQ/128, H_, B_), 256, ATT_SMEM>>>(
        Qh, Kh, Vh, biasc, density, dens_raw, att);

    // [4] O projection + residual (BM=64, grid 256): x = q + att @ wo + bo
    gemm_g64<<<dim3(8, 32), 256, GT_SMEM64>>>(2, att, wt[3], bo, q, x, nullptr, D_, D_);

    // [5] final LN
    ln_one_k<<<B_*KQ, 256>>>(x, ln_f_w, ln_f_b, lnq);

    // [6] MLP1 with GELU -> h1 fp16
    gemm_g<<<dim3(16, 16), 256, GT_SMEM128>>>(1, lnq, wt[4], b1, nullptr, nullptr, h1, 2*D_, D_);

    // [7] MLP2 + residual (BM=64, grid 256) -> out
    gemm_g64<<<dim3(8, 32), 256, GT_SMEM64>>>(2, h1, wt[5], b2, x, out, nullptr, D_, 2*D_);
}

// round 14
// speedup vs baseline: 1.5017x; 1.5017x over previous
#include <cuda_runtime.h>
#include <cuda_fp16.h>
#include <math.h>
#include <cstdint>

typedef __half f16;

// Problem constants
#define B_  2
#define KQ  1024
#define SQ  4096
#define D_  1024
#define H_  16
#define HD_ 64
#define EPSV 1e-5f

// ================= scratch (static device globals) =================
__device__ float g_x  [B_*KQ*D_];
__device__ f16   g_biasc[B_*KQ*SQ];

__device__ f16 g_lnq [B_*KQ*D_];
__device__ f16 g_lnkv[B_*SQ*D_];
__device__ f16 g_Qh[B_*KQ*D_];
__device__ f16 g_Kh[B_*SQ*D_];
__device__ f16 g_Vh[B_*SQ*D_];
__device__ f16 g_att[B_*KQ*D_];
__device__ f16 g_h1 [B_*KQ*2*D_];
__device__ f16 g_wqt[D_*D_];
__device__ f16 g_wkt[D_*D_];
__device__ f16 g_wvt[D_*D_];
__device__ f16 g_wot[D_*D_];
__device__ f16 g_w1t[2*D_*D_];
__device__ f16 g_w2t[2*D_*D_];

__device__ __forceinline__ float softplus_f(float x) {
    return fmaxf(x, 0.f) + log1pf(__expf(-fabsf(x)));
}
__device__ __forceinline__ float gelu_f(float x) {
    return 0.5f * x * (1.f + erff(x * 0.70710678118654752f));
}
__device__ __forceinline__ uint32_t smem_to_u32(const void* p) {
    uint32_t a;
    asm("{ .reg .u64 t; cvta.to.shared.u64 t, %1; cvt.u32.u64 %0, t; }" : "=r"(a) : "l"(p));
    return a;
}
__device__ __forceinline__ uint32_t cvt2_f16(float lo, float hi) {
    uint32_t r; asm("cvt.rn.f16x2.f32 %0, %1, %2;" : "=r"(r) : "f"(hi), "f"(lo)); return r;
}
__device__ __forceinline__ uint32_t ex2_h2(uint32_t t) {
    uint32_t r; asm("ex2.approx.f16x2 %0, %1;" : "=r"(r) : "r"(t)); return r;
}

// cp.async helpers
#define CP_ASYNC16(dst, src) \
    asm volatile("cp.async.cg.shared.global [%0], [%1], 16;" :: "r"(dst), "l"(src))
#define CP_COMMIT() asm volatile("cp.async.commit_group;" ::: "memory")
#define CP_WAIT3()  asm volatile("cp.async.wait_group 3;" ::: "memory")
#define CP_WAIT2()  asm volatile("cp.async.wait_group 2;" ::: "memory")
#define CP_WAIT1()  asm volatile("cp.async.wait_group 1;" ::: "memory")
#define CP_WAIT0()  asm volatile("cp.async.wait_group 0;" ::: "memory")

#define LDSM_X4(r0, r1, r2, r3, addr) \
    asm volatile("ldmatrix.sync.aligned.m8n8.x4.shared.b16 {%0,%1,%2,%3}, [%4];" \
        : "=r"(r0), "=r"(r1), "=r"(r2), "=r"(r3) : "r"(addr))
#define LDSM_X4_T(r0, r1, r2, r3, addr) \
    asm volatile("ldmatrix.sync.aligned.m8n8.x4.trans.shared.b16 {%0,%1,%2,%3}, [%4];" \
        : "=r"(r0), "=r"(r1), "=r"(r2), "=r"(r3) : "r"(addr))

#define MMA_16816(c, a, b) \
    asm volatile("mma.sync.aligned.m16n8k16.row.col.f32.f16.f16.f32 " \
        "{%0,%1,%2,%3}, {%4,%5,%6,%7}, {%8,%9}, {%0,%1,%2,%3};" \
        : "+f"((c)[0]), "+f"((c)[1]), "+f"((c)[2]), "+f"((c)[3]) \
        : "r"((a)[0]), "r"((a)[1]), "r"((a)[2]), "r"((a)[3]), "r"((b)[0]), "r"((b)[1]))

// ================= prep: weight transpose->fp16 + combined bias (f16) =========
struct PrepArgs {
    const float* wsrc[6];
    f16* wdst[6];
    int K[6]; int N[6];
    const float* ab; const float* ob; const float* pd; const float* po;
    f16* biasc;
};
__global__ void prep_k(PrepArgs a) {
    int z = blockIdx.z;
    int tx = threadIdx.x, ty = threadIdx.y;
    if (z < 6) {
        int Kd = a.K[z], Nd = a.N[z];
        int n0 = blockIdx.x * 32, k0 = blockIdx.y * 32;
        if (n0 >= Nd || k0 >= Kd) return;
        __shared__ float t[32][33];
        const float* s = a.wsrc[z];
#pragma unroll
        for (int i = 0; i < 4; i++)
            t[ty + i*8][tx] = s[(size_t)(k0 + ty + i*8) * Nd + n0 + tx];
        __syncthreads();
#pragma unroll
        for (int i = 0; i < 4; i++) {
            float v = t[tx][ty + i*8];
            a.wdst[z][(size_t)(n0 + ty + i*8) * Kd + k0 + tx] = __float2half_rn(v);
        }
    } else {
        int cta = blockIdx.y * 64 + blockIdx.x;
        int tid = ty * 32 + tx;
        float spd = softplus_f(a.pd[0]);
        float spo = softplus_f(a.po[0]);
        size_t base = (size_t)cta * 512 + tid * 2;
#pragma unroll
        for (int j = 0; j < 2; j++) {
            float4 av = ((const float4*)a.ab)[base + j];
            float4 ov = ((const float4*)a.ob)[base + j];
            __half2 h0 = __floats2half2_rn(spd*av.x + spo*ov.x, spd*av.y + spo*ov.y);
            __half2 h1 = __floats2half2_rn(spd*av.z + spo*ov.z, spd*av.w + spo*ov.w);
            ((__half2*)a.biasc)[(base + j)*2 + 0] = h0;
            ((__half2*)a.biasc)[(base + j)*2 + 1] = h1;
        }
    }
}

// ================= LayerNorm -> fp16 =================
__device__ __forceinline__ void ln_body(const float* xr, const float* w, const float* bb,
                                        f16* yr) {
    __shared__ float r0[8], r1[8];
    __shared__ float mu_s, rs_s;
    int t = threadIdx.x;
    float v[4]; float s = 0.f, s2 = 0.f;
#pragma unroll
    for (int i = 0; i < 4; i++) { float a = xr[t + i*256]; v[i] = a; s += a; s2 += a*a; }
    int lane = t & 31, wp = t >> 5;
#pragma unroll
    for (int o = 16; o; o >>= 1) {
        s  += __shfl_xor_sync(0xffffffffu, s,  o);
        s2 += __shfl_xor_sync(0xffffffffu, s2, o);
    }
    if (lane == 0) { r0[wp] = s; r1[wp] = s2; }
    __syncthreads();
    if (t == 0) {
        float ts = 0.f, t2 = 0.f;
        for (int i = 0; i < 8; i++) { ts += r0[i]; t2 += r1[i]; }
        float mu = ts * (1.f / D_);
        float var = t2 * (1.f / D_) - mu * mu;
        mu_s = mu; rs_s = rsqrtf(var + EPSV);
    }
    __syncthreads();
    float mu = mu_s, rs = rs_s;
#pragma unroll
    for (int i = 0; i < 4; i++) {
        int c = t + i*256;
        yr[c] = __float2half_rn((v[i] - mu) * rs * w[c] + bb[c]);
    }
}

__global__ void ln_all_k(const float* __restrict__ q, const float* __restrict__ kv,
                         const float* __restrict__ wq, const float* __restrict__ bq,
                         const float* __restrict__ wkv, const float* __restrict__ bkv,
                         f16* __restrict__ oq, f16* __restrict__ okv) {
    int row = blockIdx.x;
    if (row < B_*KQ) ln_body(q + (size_t)row * D_, wq, bq, oq + (size_t)row * D_);
    else {
        row -= B_*KQ;
        ln_body(kv + (size_t)row * D_, wkv, bkv, okv + (size_t)row * D_);
    }
}

__global__ void ln_one_k(const float* __restrict__ x, const float* __restrict__ w,
                         const float* __restrict__ bb, f16* __restrict__ y) {
    int row = blockIdx.x;
    ln_body(x + (size_t)row * D_, w, bb, y + (size_t)row * D_);
}

// ================= HMMA fp16 GEMM core (BM=128) ==========
// mode 1: gelu -> Chi.  mode 2: +R -> Cf fp32.  mode 4: Chi.
// mode 6: atomicAdd (+bias+R lead half).  mode 7: atomicAdd (follow half).
#define GPAD 40
#define GSTG 4
#define GABUF (128*GPAD)
#define GSTRIDE (2*GABUF*2)
#define GT_SMEM4 (GSTG*GSTRIDE)

__device__ __forceinline__ void gemm_core(
        int mode, char* gsm,
        const f16* __restrict__ Ag, const f16* __restrict__ Bg,
        const float* __restrict__ bias, const float* __restrict__ R,
        float* __restrict__ Cf, f16* __restrict__ Chi,
        int m0, int n0, int N, int Kd, int ldk) {
    int tid = threadIdx.x, lane = tid & 31, wid = tid >> 5;
    int wm = wid & 3, wn = wid >> 2;
    uint32_t sbase = smem_to_u32(gsm);

    float c[2][8][4];
#pragma unroll
    for (int i = 0; i < 2; i++)
#pragma unroll
        for (int j = 0; j < 8; j++)
#pragma unroll
            for (int q = 0; q < 4; q++) c[i][j][q] = 0.f;

    int nch = Kd >> 5;
    int lr = tid >> 2;
    int ls = (tid & 3) << 3;

    auto prefetch = [&](int ch, int buf) {
        int kc = ch << 5;
        uint32_t st = sbase + (uint32_t)buf * GSTRIDE;
        uint32_t db = st + GABUF*2;
        CP_ASYNC16(st + (lr*GPAD + ls)*2,      Ag + (size_t)(m0 + lr)      * ldk + kc + ls);
        CP_ASYNC16(st + ((lr+64)*GPAD + ls)*2, Ag + (size_t)(m0 + lr + 64) * ldk + kc + ls);
        CP_ASYNC16(db + (lr*GPAD + ls)*2,      Bg + (size_t)(n0 + lr)      * ldk + kc + ls);
        CP_ASYNC16(db + ((lr+64)*GPAD + ls)*2, Bg + (size_t)(n0 + lr + 64) * ldk + kc + ls);
    };

#pragma unroll
    for (int s = 0; s < GSTG; s++) { prefetch(s, s); CP_COMMIT(); }

    for (int it = 0; it < nch; ++it) {
        int cur = it & (GSTG - 1);
        int rem = nch - 1 - it;
        if (rem >= 3) CP_WAIT3();
        else if (rem == 2) CP_WAIT2();
        else if (rem == 1) CP_WAIT1();
        else CP_WAIT0();
        __syncthreads();

        uint32_t st = sbase + (uint32_t)cur * GSTRIDE;
        uint32_t bb = st + GABUF*2;
#pragma unroll
        for (int kk = 0; kk < 32; kk += 16) {
            uint32_t a[2][4];
#pragma unroll
            for (int mi = 0; mi < 2; mi++) {
                int row = wm*32 + mi*16 + ((lane >> 3) & 1)*8 + (lane & 7);
                int col = kk + (lane >> 4)*8;
                LDSM_X4(a[mi][0], a[mi][1], a[mi][2], a[mi][3],
                        st + (uint32_t)(row*GPAD + col)*2);
            }
            uint32_t b[8][2];
#pragma unroll
            for (int g = 0; g < 4; g++) {
                int row = wn*64 + g*16 + (lane >> 4)*8 + (lane & 7);
                int col = kk + ((lane >> 3) & 1)*8;
                uint32_t r0, r1, r2, r3;
                LDSM_X4(r0, r1, r2, r3, bb + (uint32_t)(row*GPAD + col)*2);
                b[2*g][0] = r0; b[2*g][1] = r1;
                b[2*g+1][0] = r2; b[2*g+1][1] = r3;
            }
#pragma unroll
            for (int mi = 0; mi < 2; mi++)
#pragma unroll
                for (int ni = 0; ni < 8; ni++)
                    MMA_16816(c[mi][ni], a[mi], b[ni]);
        }
        __syncthreads();
        if (it + GSTG < nch) { prefetch(it + GSTG, cur); CP_COMMIT(); }
    }

#pragma unroll
    for (int mi = 0; mi < 2; mi++) {
#pragma unroll
        for (int half = 0; half < 2; half++) {
            int row = m0 + wm*32 + mi*16 + half*8 + (lane >> 2);
#pragma unroll
            for (int ni = 0; ni < 8; ni++) {
                int col = n0 + wn*64 + ni*8 + (lane & 3)*2;
                float v0 = c[mi][ni][half*2 + 0];
                float v1 = c[mi][ni][half*2 + 1];
                size_t idx = (size_t)row * N + col;
                if (mode == 1) {
                    v0 = gelu_f(v0 + bias[col]); v1 = gelu_f(v1 + bias[col + 1]);
                    *(uint32_t*)(Chi + idx) = cvt2_f16(v0, v1);
                } else if (mode == 4) {
                    *(uint32_t*)(Chi + idx) = cvt2_f16(v0 + bias[col], v1 + bias[col + 1]);
                } else if (mode == 2) {
                    float2 r2 = *(const float2*)(R + idx);
                    float2 o2;
                    o2.x = v0 + bias[col]     + r2.x;
                    o2.y = v1 + bias[col + 1] + r2.y;
                    *(float2*)(Cf + idx) = o2;
                } else if (mode == 6) {   // split-K lead: add bias + residual
                    float2 r2 = *(const float2*)(R + idx);
                    atomicAdd(Cf + idx,     v0 + bias[col]     + r2.x);
                    atomicAdd(Cf + idx + 1, v1 + bias[col + 1] + r2.y);
                } else {                  // mode 7: split-K follow
                    atomicAdd(Cf + idx,     v0);
                    atomicAdd(Cf + idx + 1, v1);
                }
            }
        }
    }
}

__global__ void __launch_bounds__(256, 2) gemm_g(
        int mode, const f16* Ag, const f16* Bg,
        const float* bias, const float* R,
        float* Cf, f16* Chi, int N, int Kd) {
    extern __shared__ char gsm[];
    gemm_core(mode, gsm, Ag, Bg, bias, R, Cf, Chi,
              blockIdx.y * 128, blockIdx.x * 128, N, Kd, Kd);
}

// split-K GEMM: z in {0,1} selects K-half; both atomicAdd into zeroed Cf.
__global__ void __launch_bounds__(256, 2) gemm_gs(
        const f16* Ag, const f16* Bg,
        const float* bias, const float* R,
        float* Cf, int N, int Kd_half, int ldk) {
    extern __shared__ char gsm[];
    int kb = blockIdx.z * Kd_half;
    gemm_core(blockIdx.z == 0 ? 6 : 7, gsm, Ag + kb, Bg + kb, bias, R, Cf, nullptr,
              blockIdx.y * 128, blockIdx.x * 128, N, Kd_half, ldk);
}

__global__ void __launch_bounds__(256, 2) qkv_k(
        const f16* lnq, const f16* lnkv,
        const f16* wq, const f16* wk, const f16* wv,
        const float* bq, const float* bk, const float* bv,
        f16* Qh, f16* Kh, f16* Vh) {
    extern __shared__ char gsm[];
    int y = blockIdx.y;
    const f16 *A, *Bw; const float* bias; f16 *Ch; int m0;
    if (y < 16)      { A = lnq;  Bw = wq; bias = bq; Ch = Qh; m0 = y * 128; }
    else if (y < 80) { A = lnkv; Bw = wk; bias = bk; Ch = Kh; m0 = (y - 16) * 128; }
    else             { A = lnkv; Bw = wv; bias = bv; Ch = Vh; m0 = (y - 80) * 128; }
    gemm_core(4, gsm, A, Bw, bias, nullptr, nullptr, Ch,
              m0, blockIdx.x * 128, D_, D_, D_);
}

// ================= Flash attention: fixed-shift softmax, ex2.f16x2 ==========
// (round-12 proven config: 64-s iterations, 4-stage KV pipeline)
#define NIT   (SQ/64)
#define APCH  144
#define AQ_H  0
#define AKV   (128*APCH)          // 18432
#define AKVARR (64*APCH)          // 9216 per array
#define AKVBUF (2*AKVARR)         // per stage (Kh,Vh)
#define ASTG  4
#define AGATE (AKV + ASTG*AKVBUF) // 92160
#define ATT_SMEM (AGATE + 512)

#define LOG2E 1.4426950408889634f
#define MSHIFT (-4.0f * LOG2E)

__global__ void __launch_bounds__(256, 2) attn_mma_k(
        const f16* __restrict__ Qhg,
        const f16* __restrict__ Khg,
        const f16* __restrict__ Vhg,
        const f16* __restrict__ bcp, const float* __restrict__ dens,
        const float* __restrict__ p_dens,
        f16* __restrict__ Oh) {
    extern __shared__ char smem[];
    uint32_t sb = smem_to_u32(smem);
    int tid = threadIdx.x, lane = tid & 31, w = tid >> 5;
    int qt = blockIdx.x, h = blockIdx.y, b = blockIdx.z;
    int q0 = qt * 128;
    size_t qrow0 = (size_t)(b * KQ + q0);
    size_t srow0 = (size_t)(b * SQ);
    int hoff = h * 64;

    // load Q tile 128x64 into smem
#pragma unroll
    for (int i = 0; i < 4; i++) {
        int idx = tid + i*256;
        int r = idx >> 3, cc = idx & 7;
        *(uint4*)(smem + AQ_H + r*APCH + cc*16) = *(const uint4*)(Qhg + (qrow0 + r)*D_ + hoff + cc*8);
    }
    if (tid < 128) {
        float* gp = (float*)(smem + AGATE);
        gp[tid] = 1.f + tanhf(p_dens[0]) * dens[b*KQ + q0 + tid];
    }

    auto pf = [&](int s0, int buf) {
        uint32_t base = sb + AKV + buf*AKVBUF;
#pragma unroll
        for (int j = 0; j < 2; j++) {
            int rem = tid + j*256;
            int row = rem >> 3, cc = rem & 7;
            size_t goff = (srow0 + s0 + row)*D_ + hoff + cc*8;
            uint32_t soff = (uint32_t)(row*APCH + cc*16);
            CP_ASYNC16(base + 0*AKVARR + soff, Khg + goff);
            CP_ASYNC16(base + 1*AKVARR + soff, Vhg + goff);
        }
    };
    pf(0, 0);   CP_COMMIT();
    pf(64, 1);  CP_COMMIT();
    pf(128, 2); CP_COMMIT();
    pf(192, 3); CP_COMMIT();
    __syncthreads();   // Q tile + gate visible

    // preload Q fragments into registers (constant across iterations)
    uint32_t qf[4][4];
#pragma unroll
    for (int ki = 0; ki < 4; ki++) {
        uint32_t qaddr = sb + AQ_H + (uint32_t)((w*16 + (lane & 15))*APCH + (ki*16 + (lane >> 4)*8)*2);
        LDSM_X4(qf[ki][0], qf[ki][1], qf[ki][2], qf[ki][3], qaddr);
    }
    int r0 = w*16 + (lane >> 2), r1 = r0 + 8;
    float g0, g1;
    {
        float* gp = (float*)(smem + AGATE);
        g0 = gp[r0]; g1 = gp[r1];
    }
    float ga0 = g0 * 0.125f * LOG2E, gb0 = g0 * LOG2E;
    float ga1 = g1 * 0.125f * LOG2E, gb1 = g1 * LOG2E;

    float o[8][4];
#pragma unroll
    for (int i = 0; i < 8; i++)
#pragma unroll
        for (int j = 0; j < 4; j++) o[i][j] = 0.f;
    float2 l0f = {0.f, 0.f}, l1f = {0.f, 0.f};
    const f16* bp0 = bcp + (qrow0 + r0)*SQ + (lane & 3)*2;
    const f16* bp1 = bcp + (qrow0 + r1)*SQ + (lane & 3)*2;
    int cur = 0;

    for (int it = 0; it < NIT; it++) {
        int rem = NIT - 1 - it;
        if (rem >= 3) CP_WAIT3();
        else if (rem == 2) CP_WAIT2();
        else if (rem == 1) CP_WAIT1();
        else CP_WAIT0();
        __syncthreads();
        uint32_t kvb = sb + AKV + cur*AKVBUF;

#pragma unroll
        for (int sc = 0; sc < 4; sc++) {   // s-chunks of 16
            // ---- S chunk = Qh Kh ----
            float c2[2][4];
#pragma unroll
            for (int i = 0; i < 2; i++)
#pragma unroll
                for (int j = 0; j < 4; j++) c2[i][j] = 0.f;
#pragma unroll
            for (int ki = 0; ki < 4; ki++) {
                uint32_t kf[4];
                uint32_t kaddr = kvb + (uint32_t)((sc*16 + (lane & 15))*APCH + (ki*16 + (lane >> 4)*8)*2);
                LDSM_X4(kf[0], kf[1], kf[2], kf[3], kaddr);
                uint32_t B0[2] = { kf[0], kf[2] };
                uint32_t B1[2] = { kf[1], kf[3] };
                MMA_16816(c2[0], qf[ki], B0);
                MMA_16816(c2[1], qf[ki], B1);
            }
            // ---- bias + gate -> log2 domain -> ex2.f16x2 ----
            uint32_t pa[4];
#pragma unroll
            for (int half = 0; half < 2; half++) {
                int cb = it*64 + sc*16 + half*8;
                uint32_t u0 = *(const uint32_t*)(bp0 + cb);
                uint32_t u1 = *(const uint32_t*)(bp1 + cb);
                float2 b0 = __half22float2(*(const __half2*)&u0);
                float2 b1 = __half22float2(*(const __half2*)&u1);
                float t00 = fminf(fmaf(c2[half][0], ga0, fmaf(b0.x, gb0, MSHIFT)), 15.5f);
                float t01 = fminf(fmaf(c2[half][1], ga0, fmaf(b0.y, gb0, MSHIFT)), 15.5f);
                float t10 = fminf(fmaf(c2[half][2], ga1, fmaf(b1.x, gb1, MSHIFT)), 15.5f);
                float t11 = fminf(fmaf(c2[half][3], ga1, fmaf(b1.y, gb1, MSHIFT)), 15.5f);
                uint32_t p0 = ex2_h2(cvt2_f16(t00, t01));
                uint32_t p1 = ex2_h2(cvt2_f16(t10, t11));
                pa[half*2]     = p0;
                pa[half*2 + 1] = p1;
                float2 e0 = __half22float2(*(const __half2*)&p0);
                float2 e1 = __half22float2(*(const __half2*)&p1);
                l0f.x += e0.x; l0f.y += e0.y;
                l1f.x += e1.x; l1f.y += e1.y;
            }
            // ---- O += P V for this s-chunk ----
#pragma unroll
            for (int db = 0; db < 4; db++) {
                uint32_t vaddr = kvb + 1*AKVARR +
                    (uint32_t)((sc*16 + ((lane >> 3) & 1)*8 + (lane & 7))*APCH + (db*16 + (lane >> 4)*8)*2);
                uint32_t vh4[4];
                LDSM_X4_T(vh4[0], vh4[1], vh4[2], vh4[3], vaddr);
                uint32_t B0[2] = { vh4[0], vh4[1] };
                uint32_t B1[2] = { vh4[2], vh4[3] };
                MMA_16816(o[db*2],     pa, B0);
                MMA_16816(o[db*2 + 1], pa, B1);
            }
        }
        __syncthreads();
        if (it + ASTG < NIT) { pf((it + ASTG)*64, cur); CP_COMMIT(); }
        cur = (cur + 1) & (ASTG - 1);
    }

    // ---- epilogue: reduce l across the quad, normalize, store ----
    float l0 = l0f.x + l0f.y, l1 = l1f.x + l1f.y;
    l0 += __shfl_xor_sync(0xffffffffu, l0, 1);
    l0 += __shfl_xor_sync(0xffffffffu, l0, 2);
    l1 += __shfl_xor_sync(0xffffffffu, l1, 1);
    l1 += __shfl_xor_sync(0xffffffffu, l1, 2);
    float inv0 = 1.f / l0, inv1 = 1.f / l1;
#pragma unroll
    for (int nf = 0; nf < 8; nf++) {
        int d = nf*8 + (lane & 3)*2;
        size_t i0 = (qrow0 + r0)*D_ + hoff + d;
        size_t i1 = (qrow0 + r1)*D_ + hoff + d;
        *(uint32_t*)(Oh + i0) = cvt2_f16(o[nf][0]*inv0, o[nf][1]*inv0);
        *(uint32_t*)(Oh + i1) = cvt2_f16(o[nf][2]*inv1, o[nf][3]*inv1);
    }
}

// ================= launch =================
extern "C" void kernel_launch(void* const* d_in, const int* in_sizes, int n_in,
                              void* d_out, int out_size) {
    const float* q        = (const float*)d_in[0];
    const float* kv       = (const float*)d_in[1];
    const float* attn_b   = (const float*)d_in[2];
    const float* obs_b    = (const float*)d_in[3];
    const float* density  = (const float*)d_in[4];
    const float* ln_q_w   = (const float*)d_in[5];
    const float* ln_q_b   = (const float*)d_in[6];
    const float* ln_kv_w  = (const float*)d_in[7];
    const float* ln_kv_b  = (const float*)d_in[8];
    const float* wq = (const float*)d_in[9];  const float* bq = (const float*)d_in[10];
    const float* wk = (const float*)d_in[11]; const float* bk = (const float*)d_in[12];
    const float* wv = (const float*)d_in[13]; const float* bv = (const float*)d_in[14];
    const float* wo = (const float*)d_in[15]; const float* bo = (const float*)d_in[16];
    const float* dist_raw = (const float*)d_in[17];
    const float* obs_raw  = (const float*)d_in[18];
    const float* dens_raw = (const float*)d_in[19];
    const float* ln_f_w = (const float*)d_in[20]; const float* ln_f_b = (const float*)d_in[21];
    const float* w1 = (const float*)d_in[22]; const float* b1 = (const float*)d_in[23];
    const float* w2 = (const float*)d_in[24]; const float* b2 = (const float*)d_in[25];
    float* out = (float*)d_out;

    float *x;
    f16 *biasc;
    cudaGetSymbolAddress((void**)&x,   g_x);
    cudaGetSymbolAddress((void**)&biasc, g_biasc);
    f16 *lnq, *lnkv, *att, *h1, *Qh, *Kh, *Vh;
    cudaGetSymbolAddress((void**)&lnq,  g_lnq);
    cudaGetSymbolAddress((void**)&lnkv, g_lnkv);
    cudaGetSymbolAddress((void**)&att,  g_att);
    cudaGetSymbolAddress((void**)&h1,   g_h1);
    cudaGetSymbolAddress((void**)&Qh, g_Qh);
    cudaGetSymbolAddress((void**)&Kh, g_Kh);
    cudaGetSymbolAddress((void**)&Vh, g_Vh);
    f16 *wt[6];
    cudaGetSymbolAddress((void**)&wt[0], g_wqt);
    cudaGetSymbolAddress((void**)&wt[1], g_wkt);
    cudaGetSymbolAddress((void**)&wt[2], g_wvt);
    cudaGetSymbolAddress((void**)&wt[3], g_wot);
    cudaGetSymbolAddress((void**)&wt[4], g_w1t);
    cudaGetSymbolAddress((void**)&wt[5], g_w2t);

    cudaFuncSetAttribute(gemm_g,     cudaFuncAttributeMaxDynamicSharedMemorySize, GT_SMEM4);
    cudaFuncSetAttribute(gemm_gs,    cudaFuncAttributeMaxDynamicSharedMemorySize, GT_SMEM4);
    cudaFuncSetAttribute(qkv_k,      cudaFuncAttributeMaxDynamicSharedMemorySize, GT_SMEM4);
    cudaFuncSetAttribute(attn_mma_k, cudaFuncAttributeMaxDynamicSharedMemorySize, ATT_SMEM);

    // [0] prep: weight transpose -> fp16 + combined bias (f16)
    PrepArgs pa;
    pa.wsrc[0] = wq; pa.wsrc[1] = wk; pa.wsrc[2] = wv; pa.wsrc[3] = wo; pa.wsrc[4] = w1; pa.wsrc[5] = w2;
    for (int i = 0; i < 6; i++) pa.wdst[i] = wt[i];
    pa.K[0]=1024; pa.K[1]=1024; pa.K[2]=1024; pa.K[3]=1024; pa.K[4]=1024; pa.K[5]=2048;
    pa.N[0]=1024; pa.N[1]=1024; pa.N[2]=1024; pa.N[3]=1024; pa.N[4]=2048; pa.N[5]=1024;
    pa.ab = attn_b; pa.ob = obs_b; pa.pd = dist_raw; pa.po = obs_raw; pa.biasc = biasc;
    prep_k<<<dim3(64, 64, 7), dim3(32, 8)>>>(pa);

    // [1] both input LayerNorms -> fp16
    ln_all_k<<<B_*(KQ + SQ), 256>>>(q, kv, ln_q_w, ln_q_b, ln_kv_w, ln_kv_b, lnq, lnkv);

    // [2] fused Q/K/V projections
    qkv_k<<<dim3(8, 144), 256, GT_SMEM4>>>(lnq, lnkv, wt[0], wt[1], wt[2],
                                           bq, bk, bv, Qh, Kh, Vh);

    // [3] flash attention -> att fp16   (captured by ncu)
    attn_mma_k<<<dim3(KQ/128, H_, B_), 256, ATT_SMEM>>>(
        Qh, Kh, Vh, biasc, density, dens_raw, att);

    // [4] O projection + residual (split-K, grid 256): x = q + att @ wo + bo
    cudaMemsetAsync(x, 0, (size_t)B_*KQ*D_*sizeof(float));
    gemm_gs<<<dim3(8, 16, 2), 256, GT_SMEM4>>>(att, wt[3], bo, q, x, D_, 512, D_);

    // [5] final LN
    ln_one_k<<<B_*KQ, 256>>>(x, ln_f_w, ln_f_b, lnq);

    // [6] MLP1 with GELU -> h1 fp16
    gemm_g<<<dim3(16, 16), 256, GT_SMEM4>>>(1, lnq, wt[4], b1, nullptr, nullptr, h1, 2*D_, D_);

    // [7] MLP2 + residual (split-K, grid 256) -> out
    cudaMemsetAsync(out, 0, (size_t)B_*KQ*D_*sizeof(float));
    gemm_gs<<<dim3(8, 16, 2), 256, GT_SMEM4>>>(h1, wt[5], b2, x, out, D_, 1024, 2*D_);
}

// round 15
// speedup vs baseline: 1.6239x; 1.0813x over previous
#include <cuda_runtime.h>
#include <cuda_fp16.h>
#include <math.h>
#include <cstdint>

typedef __half f16;

// Problem constants
#define B_  2
#define KQ  1024
#define SQ  4096
#define D_  1024
#define H_  16
#define HD_ 64
#define EPSV 1e-5f

// ================= scratch (static device globals) =================
__device__ float g_x  [B_*KQ*D_];
__device__ f16   g_biasc[B_*KQ*SQ];

__device__ f16 g_lnq [B_*KQ*D_];
__device__ f16 g_lnkv[B_*SQ*D_];
__device__ f16 g_Qh[B_*KQ*D_];
__device__ f16 g_Kh[B_*SQ*D_];
__device__ f16 g_Vh[B_*SQ*D_];
__device__ f16 g_att[B_*KQ*D_];
__device__ f16 g_h1 [B_*KQ*2*D_];
__device__ f16 g_wqt[D_*D_];
__device__ f16 g_wkt[D_*D_];
__device__ f16 g_wvt[D_*D_];
__device__ f16 g_wot[D_*D_];
__device__ f16 g_w1t[2*D_*D_];
__device__ f16 g_w2t[2*D_*D_];

__device__ __forceinline__ float softplus_f(float x) {
    return fmaxf(x, 0.f) + log1pf(__expf(-fabsf(x)));
}
__device__ __forceinline__ float gelu_f(float x) {
    return 0.5f * x * (1.f + erff(x * 0.70710678118654752f));
}
__device__ __forceinline__ uint32_t smem_to_u32(const void* p) {
    uint32_t a;
    asm("{ .reg .u64 t; cvta.to.shared.u64 t, %1; cvt.u32.u64 %0, t; }" : "=r"(a) : "l"(p));
    return a;
}
__device__ __forceinline__ uint32_t cvt2_f16(float lo, float hi) {
    uint32_t r; asm("cvt.rn.f16x2.f32 %0, %1, %2;" : "=r"(r) : "f"(hi), "f"(lo)); return r;
}
__device__ __forceinline__ uint32_t ex2_h2(uint32_t t) {
    uint32_t r; asm("ex2.approx.f16x2 %0, %1;" : "=r"(r) : "r"(t)); return r;
}

// cp.async helpers
#define CP_ASYNC16(dst, src) \
    asm volatile("cp.async.cg.shared.global [%0], [%1], 16;" :: "r"(dst), "l"(src))
#define CP_COMMIT() asm volatile("cp.async.commit_group;" ::: "memory")
#define CP_WAIT3()  asm volatile("cp.async.wait_group 3;" ::: "memory")
#define CP_WAIT2()  asm volatile("cp.async.wait_group 2;" ::: "memory")
#define CP_WAIT1()  asm volatile("cp.async.wait_group 1;" ::: "memory")
#define CP_WAIT0()  asm volatile("cp.async.wait_group 0;" ::: "memory")

#define LDSM_X4(r0, r1, r2, r3, addr) \
    asm volatile("ldmatrix.sync.aligned.m8n8.x4.shared.b16 {%0,%1,%2,%3}, [%4];" \
        : "=r"(r0), "=r"(r1), "=r"(r2), "=r"(r3) : "r"(addr))
#define LDSM_X4_T(r0, r1, r2, r3, addr) \
    asm volatile("ldmatrix.sync.aligned.m8n8.x4.trans.shared.b16 {%0,%1,%2,%3}, [%4];" \
        : "=r"(r0), "=r"(r1), "=r"(r2), "=r"(r3) : "r"(addr))

#define MMA_16816(c, a, b) \
    asm volatile("mma.sync.aligned.m16n8k16.row.col.f32.f16.f16.f32 " \
        "{%0,%1,%2,%3}, {%4,%5,%6,%7}, {%8,%9}, {%0,%1,%2,%3};" \
        : "+f"((c)[0]), "+f"((c)[1]), "+f"((c)[2]), "+f"((c)[3]) \
        : "r"((a)[0]), "r"((a)[1]), "r"((a)[2]), "r"((a)[3]), "r"((b)[0]), "r"((b)[1]))

// ================= prep: weight transpose->fp16 + combined bias (f16) =========
struct PrepArgs {
    const float* wsrc[6];
    f16* wdst[6];
    int K[6]; int N[6];
    const float* ab; const float* ob; const float* pd; const float* po;
    f16* biasc;
};
__global__ void prep_k(PrepArgs a) {
    int z = blockIdx.z;
    int tx = threadIdx.x, ty = threadIdx.y;
    if (z < 6) {
        int Kd = a.K[z], Nd = a.N[z];
        int n0 = blockIdx.x * 32, k0 = blockIdx.y * 32;
        if (n0 >= Nd || k0 >= Kd) return;
        __shared__ float t[32][33];
        const float* s = a.wsrc[z];
#pragma unroll
        for (int i = 0; i < 4; i++)
            t[ty + i*8][tx] = s[(size_t)(k0 + ty + i*8) * Nd + n0 + tx];
        __syncthreads();
#pragma unroll
        for (int i = 0; i < 4; i++) {
            float v = t[tx][ty + i*8];
            a.wdst[z][(size_t)(n0 + ty + i*8) * Kd + k0 + tx] = __float2half_rn(v);
        }
    } else {
        int cta = blockIdx.y * 64 + blockIdx.x;
        int tid = ty * 32 + tx;
        float spd = softplus_f(a.pd[0]);
        float spo = softplus_f(a.po[0]);
        size_t base = (size_t)cta * 512 + tid * 2;
#pragma unroll
        for (int j = 0; j < 2; j++) {
            float4 av = ((const float4*)a.ab)[base + j];
            float4 ov = ((const float4*)a.ob)[base + j];
            __half2 h0 = __floats2half2_rn(spd*av.x + spo*ov.x, spd*av.y + spo*ov.y);
            __half2 h1 = __floats2half2_rn(spd*av.z + spo*ov.z, spd*av.w + spo*ov.w);
            ((__half2*)a.biasc)[(base + j)*2 + 0] = h0;
            ((__half2*)a.biasc)[(base + j)*2 + 1] = h1;
        }
    }
}

// ================= LayerNorm -> fp16 =================
__device__ __forceinline__ void ln_body(const float* xr, const float* w, const float* bb,
                                        f16* yr) {
    __shared__ float r0[8], r1[8];
    __shared__ float mu_s, rs_s;
    int t = threadIdx.x;
    float v[4]; float s = 0.f, s2 = 0.f;
#pragma unroll
    for (int i = 0; i < 4; i++) { float a = xr[t + i*256]; v[i] = a; s += a; s2 += a*a; }
    int lane = t & 31, wp = t >> 5;
#pragma unroll
    for (int o = 16; o; o >>= 1) {
        s  += __shfl_xor_sync(0xffffffffu, s,  o);
        s2 += __shfl_xor_sync(0xffffffffu, s2, o);
    }
    if (lane == 0) { r0[wp] = s; r1[wp] = s2; }
    __syncthreads();
    if (t == 0) {
        float ts = 0.f, t2 = 0.f;
        for (int i = 0; i < 8; i++) { ts += r0[i]; t2 += r1[i]; }
        float mu = ts * (1.f / D_);
        float var = t2 * (1.f / D_) - mu * mu;
        mu_s = mu; rs_s = rsqrtf(var + EPSV);
    }
    __syncthreads();
    float mu = mu_s, rs = rs_s;
#pragma unroll
    for (int i = 0; i < 4; i++) {
        int c = t + i*256;
        yr[c] = __float2half_rn((v[i] - mu) * rs * w[c] + bb[c]);
    }
}

__global__ void ln_all_k(const float* __restrict__ q, const float* __restrict__ kv,
                         const float* __restrict__ wq, const float* __restrict__ bq,
                         const float* __restrict__ wkv, const float* __restrict__ bkv,
                         f16* __restrict__ oq, f16* __restrict__ okv) {
    int row = blockIdx.x;
    if (row < B_*KQ) ln_body(q + (size_t)row * D_, wq, bq, oq + (size_t)row * D_);
    else {
        row -= B_*KQ;
        ln_body(kv + (size_t)row * D_, wkv, bkv, okv + (size_t)row * D_);
    }
}

__global__ void ln_one_k(const float* __restrict__ x, const float* __restrict__ w,
                         const float* __restrict__ bb, f16* __restrict__ y) {
    int row = blockIdx.x;
    ln_body(x + (size_t)row * D_, w, bb, y + (size_t)row * D_);
}

// ================= HMMA fp16 GEMM core (BM=128, BK=64) ==========
// mode 1: gelu -> Chi.  mode 2: +R -> Cf fp32.  mode 4: Chi.
// mode 6: atomicAdd (+bias+R lead half).  mode 7: atomicAdd (follow half).
#define GPADG 72                    // f16 row pitch for 64-col rows (144 B)
#define GSTG 3
#define GABUF (128*GPADG)           // 9216 f16 per array per stage
#define GSTRIDE (2*GABUF*2)         // 36864 B per stage (A,B)
#define GT_SMEM4 (GSTG*GSTRIDE)     // 110592 B

__device__ __forceinline__ void gemm_core(
        int mode, char* gsm,
        const f16* __restrict__ Ag, const f16* __restrict__ Bg,
        const float* __restrict__ bias, const float* __restrict__ R,
        float* __restrict__ Cf, f16* __restrict__ Chi,
        int m0, int n0, int N, int Kd, int ldk) {
    int tid = threadIdx.x, lane = tid & 31, wid = tid >> 5;
    int wm = wid & 3, wn = wid >> 2;
    uint32_t sbase = smem_to_u32(gsm);

    float c[2][8][4];
#pragma unroll
    for (int i = 0; i < 2; i++)
#pragma unroll
        for (int j = 0; j < 8; j++)
#pragma unroll
            for (int q = 0; q < 4; q++) c[i][j][q] = 0.f;

    int nch = Kd >> 6;                 // 64-wide k-chunks
    int lr = tid >> 3;                 // 0..31
    int ls = (tid & 7) << 3;           // 0,8,..,56

    auto prefetch = [&](int ch, int buf) {
        int kc = ch << 6;
        uint32_t st = sbase + (uint32_t)buf * GSTRIDE;
        uint32_t db = st + GABUF*2;
#pragma unroll
        for (int r4 = 0; r4 < 4; r4++) {
            int row = lr + r4*32;
            CP_ASYNC16(st + (uint32_t)(row*GPADG + ls)*2,
                       Ag + (size_t)(m0 + row) * ldk + kc + ls);
            CP_ASYNC16(db + (uint32_t)(row*GPADG + ls)*2,
                       Bg + (size_t)(n0 + row) * ldk + kc + ls);
        }
    };

#pragma unroll
    for (int s = 0; s < GSTG; s++) { prefetch(s, s); CP_COMMIT(); }

    int cur = 0;
    for (int it = 0; it < nch; ++it) {
        int rem = nch - 1 - it;
        if (rem >= 2) CP_WAIT2();
        else if (rem == 1) CP_WAIT1();
        else CP_WAIT0();
        __syncthreads();

        uint32_t st = sbase + (uint32_t)cur * GSTRIDE;
        uint32_t bb = st + GABUF*2;
#pragma unroll
        for (int kk = 0; kk < 64; kk += 16) {
            uint32_t a[2][4];
#pragma unroll
            for (int mi = 0; mi < 2; mi++) {
                int row = wm*32 + mi*16 + ((lane >> 3) & 1)*8 + (lane & 7);
                int col = kk + (lane >> 4)*8;
                LDSM_X4(a[mi][0], a[mi][1], a[mi][2], a[mi][3],
                        st + (uint32_t)(row*GPADG + col)*2);
            }
            uint32_t b[8][2];
#pragma unroll
            for (int g = 0; g < 4; g++) {
                int row = wn*64 + g*16 + (lane >> 4)*8 + (lane & 7);
                int col = kk + ((lane >> 3) & 1)*8;
                uint32_t r0, r1, r2, r3;
                LDSM_X4(r0, r1, r2, r3, bb + (uint32_t)(row*GPADG + col)*2);
                b[2*g][0] = r0; b[2*g][1] = r1;
                b[2*g+1][0] = r2; b[2*g+1][1] = r3;
            }
#pragma unroll
            for (int mi = 0; mi < 2; mi++)
#pragma unroll
                for (int ni = 0; ni < 8; ni++)
                    MMA_16816(c[mi][ni], a[mi], b[ni]);
        }
        __syncthreads();
        if (it + GSTG < nch) { prefetch(it + GSTG, cur); CP_COMMIT(); }
        cur = (cur + 1 == GSTG) ? 0 : cur + 1;
    }

#pragma unroll
    for (int mi = 0; mi < 2; mi++) {
#pragma unroll
        for (int half = 0; half < 2; half++) {
            int row = m0 + wm*32 + mi*16 + half*8 + (lane >> 2);
#pragma unroll
            for (int ni = 0; ni < 8; ni++) {
                int col = n0 + wn*64 + ni*8 + (lane & 3)*2;
                float v0 = c[mi][ni][half*2 + 0];
                float v1 = c[mi][ni][half*2 + 1];
                size_t idx = (size_t)row * N + col;
                if (mode == 1) {
                    v0 = gelu_f(v0 + bias[col]); v1 = gelu_f(v1 + bias[col + 1]);
                    *(uint32_t*)(Chi + idx) = cvt2_f16(v0, v1);
                } else if (mode == 4) {
                    *(uint32_t*)(Chi + idx) = cvt2_f16(v0 + bias[col], v1 + bias[col + 1]);
                } else if (mode == 2) {
                    float2 r2 = *(const float2*)(R + idx);
                    float2 o2;
                    o2.x = v0 + bias[col]     + r2.x;
                    o2.y = v1 + bias[col + 1] + r2.y;
                    *(float2*)(Cf + idx) = o2;
                } else if (mode == 6) {   // split-K lead: add bias + residual
                    float2 r2 = *(const float2*)(R + idx);
                    atomicAdd(Cf + idx,     v0 + bias[col]     + r2.x);
                    atomicAdd(Cf + idx + 1, v1 + bias[col + 1] + r2.y);
                } else {                  // mode 7: split-K follow
                    atomicAdd(Cf + idx,     v0);
                    atomicAdd(Cf + idx + 1, v1);
                }
            }
        }
    }
}

__global__ void __launch_bounds__(256, 2) gemm_g(
        int mode, const f16* Ag, const f16* Bg,
        const float* bias, const float* R,
        float* Cf, f16* Chi, int N, int Kd) {
    extern __shared__ char gsm[];
    gemm_core(mode, gsm, Ag, Bg, bias, R, Cf, Chi,
              blockIdx.y * 128, blockIdx.x * 128, N, Kd, Kd);
}

// split-K GEMM: z in {0,1} selects K-half; both atomicAdd into zeroed Cf.
__global__ void __launch_bounds__(256, 2) gemm_gs(
        const f16* Ag, const f16* Bg,
        const float* bias, const float* R,
        float* Cf, int N, int Kd_half, int ldk) {
    extern __shared__ char gsm[];
    int kb = blockIdx.z * Kd_half;
    gemm_core(blockIdx.z == 0 ? 6 : 7, gsm, Ag + kb, Bg + kb, bias, R, Cf, nullptr,
              blockIdx.y * 128, blockIdx.x * 128, N, Kd_half, ldk);
}

__global__ void __launch_bounds__(256, 2) qkv_k(
        const f16* lnq, const f16* lnkv,
        const f16* wq, const f16* wk, const f16* wv,
        const float* bq, const float* bk, const float* bv,
        f16* Qh, f16* Kh, f16* Vh) {
    extern __shared__ char gsm[];
    int y = blockIdx.y;
    const f16 *A, *Bw; const float* bias; f16 *Ch; int m0;
    if (y < 16)      { A = lnq;  Bw = wq; bias = bq; Ch = Qh; m0 = y * 128; }
    else if (y < 80) { A = lnkv; Bw = wk; bias = bk; Ch = Kh; m0 = (y - 16) * 128; }
    else             { A = lnkv; Bw = wv; bias = bv; Ch = Vh; m0 = (y - 80) * 128; }
    gemm_core(4, gsm, A, Bw, bias, nullptr, nullptr, Ch,
              m0, blockIdx.x * 128, D_, D_, D_);
}

// ================= Flash attention: fixed-shift softmax, ex2.f16x2 ==========
// (proven config: 64-s iterations, 4-stage KV pipeline)
#define NIT   (SQ/64)
#define APCH  144
#define AQ_H  0
#define AKV   (128*APCH)          // 18432
#define AKVARR (64*APCH)          // 9216 per array
#define AKVBUF (2*AKVARR)         // per stage (Kh,Vh)
#define ASTG  4
#define AGATE (AKV + ASTG*AKVBUF) // 92160
#define ATT_SMEM (AGATE + 512)

#define LOG2E 1.4426950408889634f
#define MSHIFT (-4.0f * LOG2E)

__global__ void __launch_bounds__(256, 2) attn_mma_k(
        const f16* __restrict__ Qhg,
        const f16* __restrict__ Khg,
        const f16* __restrict__ Vhg,
        const f16* __restrict__ bcp, const float* __restrict__ dens,
        const float* __restrict__ p_dens,
        f16* __restrict__ Oh) {
    extern __shared__ char smem[];
    uint32_t sb = smem_to_u32(smem);
    int tid = threadIdx.x, lane = tid & 31, w = tid >> 5;
    int qt = blockIdx.x, h = blockIdx.y, b = blockIdx.z;
    int q0 = qt * 128;
    size_t qrow0 = (size_t)(b * KQ + q0);
    size_t srow0 = (size_t)(b * SQ);
    int hoff = h * 64;

    // load Q tile 128x64 into smem
#pragma unroll
    for (int i = 0; i < 4; i++) {
        int idx = tid + i*256;
        int r = idx >> 3, cc = idx & 7;
        *(uint4*)(smem + AQ_H + r*APCH + cc*16) = *(const uint4*)(Qhg + (qrow0 + r)*D_ + hoff + cc*8);
    }
    if (tid < 128) {
        float* gp = (float*)(smem + AGATE);
        gp[tid] = 1.f + tanhf(p_dens[0]) * dens[b*KQ + q0 + tid];
    }

    auto pf = [&](int s0, int buf) {
        uint32_t base = sb + AKV + buf*AKVBUF;
#pragma unroll
        for (int j = 0; j < 2; j++) {
            int rem = tid + j*256;
            int row = rem >> 3, cc = rem & 7;
            size_t goff = (srow0 + s0 + row)*D_ + hoff + cc*8;
            uint32_t soff = (uint32_t)(row*APCH + cc*16);
            CP_ASYNC16(base + 0*AKVARR + soff, Khg + goff);
            CP_ASYNC16(base + 1*AKVARR + soff, Vhg + goff);
        }
    };
    pf(0, 0);   CP_COMMIT();
    pf(64, 1);  CP_COMMIT();
    pf(128, 2); CP_COMMIT();
    pf(192, 3); CP_COMMIT();
    __syncthreads();   // Q tile + gate visible

    // preload Q fragments into registers (constant across iterations)
    uint32_t qf[4][4];
#pragma unroll
    for (int ki = 0; ki < 4; ki++) {
        uint32_t qaddr = sb + AQ_H + (uint32_t)((w*16 + (lane & 15))*APCH + (ki*16 + (lane >> 4)*8)*2);
        LDSM_X4(qf[ki][0], qf[ki][1], qf[ki][2], qf[ki][3], qaddr);
    }
    int r0 = w*16 + (lane >> 2), r1 = r0 + 8;
    float g0, g1;
    {
        float* gp = (float*)(smem + AGATE);
        g0 = gp[r0]; g1 = gp[r1];
    }
    float ga0 = g0 * 0.125f * LOG2E, gb0 = g0 * LOG2E;
    float ga1 = g1 * 0.125f * LOG2E, gb1 = g1 * LOG2E;

    float o[8][4];
#pragma unroll
    for (int i = 0; i < 8; i++)
#pragma unroll
        for (int j = 0; j < 4; j++) o[i][j] = 0.f;
    float2 l0f = {0.f, 0.f}, l1f = {0.f, 0.f};
    const f16* bp0 = bcp + (qrow0 + r0)*SQ + (lane & 3)*2;
    const f16* bp1 = bcp + (qrow0 + r1)*SQ + (lane & 3)*2;
    int cur = 0;

    for (int it = 0; it < NIT; it++) {
        int rem = NIT - 1 - it;
        if (rem >= 3) CP_WAIT3();
        else if (rem == 2) CP_WAIT2();
        else if (rem == 1) CP_WAIT1();
        else CP_WAIT0();
        __syncthreads();
        uint32_t kvb = sb + AKV + cur*AKVBUF;

#pragma unroll
        for (int sc = 0; sc < 4; sc++) {   // s-chunks of 16
            // ---- S chunk = Qh Kh ----
            float c2[2][4];
#pragma unroll
            for (int i = 0; i < 2; i++)
#pragma unroll
                for (int j = 0; j < 4; j++) c2[i][j] = 0.f;
#pragma unroll
            for (int ki = 0; ki < 4; ki++) {
                uint32_t kf[4];
                uint32_t kaddr = kvb + (uint32_t)((sc*16 + (lane & 15))*APCH + (ki*16 + (lane >> 4)*8)*2);
                LDSM_X4(kf[0], kf[1], kf[2], kf[3], kaddr);
                uint32_t B0[2] = { kf[0], kf[2] };
                uint32_t B1[2] = { kf[1], kf[3] };
                MMA_16816(c2[0], qf[ki], B0);
                MMA_16816(c2[1], qf[ki], B1);
            }
            // ---- bias + gate -> log2 domain -> ex2.f16x2 ----
            uint32_t pa[4];
#pragma unroll
            for (int half = 0; half < 2; half++) {
                int cb = it*64 + sc*16 + half*8;
                uint32_t u0 = *(const uint32_t*)(bp0 + cb);
                uint32_t u1 = *(const uint32_t*)(bp1 + cb);
                float2 b0 = __half22float2(*(const __half2*)&u0);
                float2 b1 = __half22float2(*(const __half2*)&u1);
                float t00 = fminf(fmaf(c2[half][0], ga0, fmaf(b0.x, gb0, MSHIFT)), 15.5f);
                float t01 = fminf(fmaf(c2[half][1], ga0, fmaf(b0.y, gb0, MSHIFT)), 15.5f);
                float t10 = fminf(fmaf(c2[half][2], ga1, fmaf(b1.x, gb1, MSHIFT)), 15.5f);
                float t11 = fminf(fmaf(c2[half][3], ga1, fmaf(b1.y, gb1, MSHIFT)), 15.5f);
                uint32_t p0 = ex2_h2(cvt2_f16(t00, t01));
                uint32_t p1 = ex2_h2(cvt2_f16(t10, t11));
                pa[half*2]     = p0;
                pa[half*2 + 1] = p1;
                float2 e0 = __half22float2(*(const __half2*)&p0);
                float2 e1 = __half22float2(*(const __half2*)&p1);
                l0f.x += e0.x; l0f.y += e0.y;
                l1f.x += e1.x; l1f.y += e1.y;
            }
            // ---- O += P V for this s-chunk ----
#pragma unroll
            for (int db = 0; db < 4; db++) {
                uint32_t vaddr = kvb + 1*AKVARR +
                    (uint32_t)((sc*16 + ((lane >> 3) & 1)*8 + (lane & 7))*APCH + (db*16 + (lane >> 4)*8)*2);
                uint32_t vh4[4];
                LDSM_X4_T(vh4[0], vh4[1], vh4[2], vh4[3], vaddr);
                uint32_t B0[2] = { vh4[0], vh4[1] };
                uint32_t B1[2] = { vh4[2], vh4[3] };
                MMA_16816(o[db*2],     pa, B0);
                MMA_16816(o[db*2 + 1], pa, B1);
            }
        }
        __syncthreads();
        if (it + ASTG < NIT) { pf((it + ASTG)*64, cur); CP_COMMIT(); }
        cur = (cur + 1) & (ASTG - 1);
    }

    // ---- epilogue: reduce l across the quad, normalize, store ----
    float l0 = l0f.x + l0f.y, l1 = l1f.x + l1f.y;
    l0 += __shfl_xor_sync(0xffffffffu, l0, 1);
    l0 += __shfl_xor_sync(0xffffffffu, l0, 2);
    l1 += __shfl_xor_sync(0xffffffffu, l1, 1);
    l1 += __shfl_xor_sync(0xffffffffu, l1, 2);
    float inv0 = 1.f / l0, inv1 = 1.f / l1;
#pragma unroll
    for (int nf = 0; nf < 8; nf++) {
        int d = nf*8 + (lane & 3)*2;
        size_t i0 = (qrow0 + r0)*D_ + hoff + d;
        size_t i1 = (qrow0 + r1)*D_ + hoff + d;
        *(uint32_t*)(Oh + i0) = cvt2_f16(o[nf][0]*inv0, o[nf][1]*inv0);
        *(uint32_t*)(Oh + i1) = cvt2_f16(o[nf][2]*inv1, o[nf][3]*inv1);
    }
}

// ================= launch =================
extern "C" void kernel_launch(void* const* d_in, const int* in_sizes, int n_in,
                              void* d_out, int out_size) {
    const float* q        = (const float*)d_in[0];
    const float* kv       = (const float*)d_in[1];
    const float* attn_b   = (const float*)d_in[2];
    const float* obs_b    = (const float*)d_in[3];
    const float* density  = (const float*)d_in[4];
    const float* ln_q_w   = (const float*)d_in[5];
    const float* ln_q_b   = (const float*)d_in[6];
    const float* ln_kv_w  = (const float*)d_in[7];
    const float* ln_kv_b  = (const float*)d_in[8];
    const float* wq = (const float*)d_in[9];  const float* bq = (const float*)d_in[10];
    const float* wk = (const float*)d_in[11]; const float* bk = (const float*)d_in[12];
    const float* wv = (const float*)d_in[13]; const float* bv = (const float*)d_in[14];
    const float* wo = (const float*)d_in[15]; const float* bo = (const float*)d_in[16];
    const float* dist_raw = (const float*)d_in[17];
    const float* obs_raw  = (const float*)d_in[18];
    const float* dens_raw = (const float*)d_in[19];
    const float* ln_f_w = (const float*)d_in[20]; const float* ln_f_b = (const float*)d_in[21];
    const float* w1 = (const float*)d_in[22]; const float* b1 = (const float*)d_in[23];
    const float* w2 = (const float*)d_in[24]; const float* b2 = (const float*)d_in[25];
    float* out = (float*)d_out;

    float *x;
    f16 *biasc;
    cudaGetSymbolAddress((void**)&x,   g_x);
    cudaGetSymbolAddress((void**)&biasc, g_biasc);
    f16 *lnq, *lnkv, *att, *h1, *Qh, *Kh, *Vh;
    cudaGetSymbolAddress((void**)&lnq,  g_lnq);
    cudaGetSymbolAddress((void**)&lnkv, g_lnkv);
    cudaGetSymbolAddress((void**)&att,  g_att);
    cudaGetSymbolAddress((void**)&h1,   g_h1);
    cudaGetSymbolAddress((void**)&Qh, g_Qh);
    cudaGetSymbolAddress((void**)&Kh, g_Kh);
    cudaGetSymbolAddress((void**)&Vh, g_Vh);
    f16 *wt[6];
    cudaGetSymbolAddress((void**)&wt[0], g_wqt);
    cudaGetSymbolAddress((void**)&wt[1], g_wkt);
    cudaGetSymbolAddress((void**)&wt[2], g_wvt);
    cudaGetSymbolAddress((void**)&wt[3], g_wot);
    cudaGetSymbolAddress((void**)&wt[4], g_w1t);
    cudaGetSymbolAddress((void**)&wt[5], g_w2t);

    cudaFuncSetAttribute(gemm_g,     cudaFuncAttributeMaxDynamicSharedMemorySize, GT_SMEM4);
    cudaFuncSetAttribute(gemm_gs,    cudaFuncAttributeMaxDynamicSharedMemorySize, GT_SMEM4);
    cudaFuncSetAttribute(qkv_k,      cudaFuncAttributeMaxDynamicSharedMemorySize, GT_SMEM4);
    cudaFuncSetAttribute(attn_mma_k, cudaFuncAttributeMaxDynamicSharedMemorySize, ATT_SMEM);

    // [0] prep: weight transpose -> fp16 + combined bias (f16)
    PrepArgs pa;
    pa.wsrc[0] = wq; pa.wsrc[1] = wk; pa.wsrc[2] = wv; pa.wsrc[3] = wo; pa.wsrc[4] = w1; pa.wsrc[5] = w2;
    for (int i = 0; i < 6; i++) pa.wdst[i] = wt[i];
    pa.K[0]=1024; pa.K[1]=1024; pa.K[2]=1024; pa.K[3]=1024; pa.K[4]=1024; pa.K[5]=2048;
    pa.N[0]=1024; pa.N[1]=1024; pa.N[2]=1024; pa.N[3]=1024; pa.N[4]=2048; pa.N[5]=1024;
    pa.ab = attn_b; pa.ob = obs_b; pa.pd = dist_raw; pa.po = obs_raw; pa.biasc = biasc;
    prep_k<<<dim3(64, 64, 7), dim3(32, 8)>>>(pa);

    // [1] both input LayerNorms -> fp16
    ln_all_k<<<B_*(KQ + SQ), 256>>>(q, kv, ln_q_w, ln_q_b, ln_kv_w, ln_kv_b, lnq, lnkv);

    // [2] fused Q/K/V projections (BK=64: 16 iters/CTA)
    qkv_k<<<dim3(8, 144), 256, GT_SMEM4>>>(lnq, lnkv, wt[0], wt[1], wt[2],
                                           bq, bk, bv, Qh, Kh, Vh);

    // [3] flash attention -> att fp16   (captured by ncu)
    attn_mma_k<<<dim3(KQ/128, H_, B_), 256, ATT_SMEM>>>(
        Qh, Kh, Vh, biasc, density, dens_raw, att);

    // [4] O projection + residual (split-K, grid 256, 8 iters/CTA)
    cudaMemsetAsync(x, 0, (size_t)B_*KQ*D_*sizeof(float));
    gemm_gs<<<dim3(8, 16, 2), 256, GT_SMEM4>>>(att, wt[3], bo, q, x, D_, 512, D_);

    // [5] final LN
    ln_one_k<<<B_*KQ, 256>>>(x, ln_f_w, ln_f_b, lnq);

    // [6] MLP1 with GELU -> h1 fp16 (16 iters/CTA)
    gemm_g<<<dim3(16, 16), 256, GT_SMEM4>>>(1, lnq, wt[4], b1, nullptr, nullptr, h1, 2*D_, D_);

    // [7] MLP2 + residual (split-K, grid 256, 16 iters/CTA) -> out
    cudaMemsetAsync(out, 0, (size_t)B_*KQ*D_*sizeof(float));
    gemm_gs<<<dim3(8, 16, 2), 256, GT_SMEM4>>>(h1, wt[5], b2, x, out, D_, 1024, 2*D_);
}